// round 2
// baseline (speedup 1.0000x reference)
#include <cuda_runtime.h>

#define NQ       12
#define DIM      4096           // 2^12
#define NLAYERS  6
#define NGATES   (NLAYERS * NQ) // 72
#define THREADS  256
#define APT      (DIM / THREADS) // 16 amplitudes per thread

__device__ __forceinline__ float2 cmul(float2 a, float2 b) {
    return make_float2(fmaf(a.x, b.x, -a.y * b.y),
                       fmaf(a.x, b.y,  a.y * b.x));
}
__device__ __forceinline__ float2 cfma(float2 a, float2 b, float2 c) {
    // a*b + c
    return make_float2(fmaf(a.x, b.x, fmaf(-a.y, b.y, c.x)),
                       fmaf(a.x, b.y, fmaf( a.y, b.x, c.y)));
}

__global__ __launch_bounds__(THREADS)
void qsim_kernel(const float* __restrict__ x,
                 const float* __restrict__ params,
                 float* __restrict__ out) {
    __shared__ float2 sAmp[DIM];          // 32 KB statevector
    __shared__ float2 sGate[NGATES * 4];  // 72 Rot gates (2x2 complex)
    __shared__ float  sc[NQ], ssn[NQ];    // cos(x/2), sin(x/2)
    __shared__ float2 sL[16];             // product table, qubits 8..11
    __shared__ float  sExp[NQ];           // <Z_q> accumulators

    const int tid = threadIdx.x;
    const int b   = blockIdx.x;

    // ---- stage 0: per-sample trig, gate matrices, accumulator clear ----
    if (tid < NQ) {
        float xv = x[b * NQ + tid];
        sc[tid]  = cosf(0.5f * xv);
        ssn[tid] = sinf(0.5f * xv);
        sExp[tid] = 0.0f;
    }
    if (tid < NGATES) {
        float phi = params[tid * 3 + 0];
        float th  = params[tid * 3 + 1];
        float om  = params[tid * 3 + 2];
        float ct = cosf(0.5f * th), st = sinf(0.5f * th);
        float a  = 0.5f * (phi + om), bb = 0.5f * (phi - om);
        float ca = cosf(a),  sa = sinf(a);
        float cb = cosf(bb), sb = sinf(bb);
        // Rot = [[ep*ct, -em*st], [conj(em)*st, conj(ep)*ct]]
        // ep = ca - i sa ; em = cb + i sb
        sGate[tid * 4 + 0] = make_float2( ca * ct, -sa * ct);
        sGate[tid * 4 + 1] = make_float2(-cb * st, -sb * st);
        sGate[tid * 4 + 2] = make_float2( cb * st, -sb * st);
        sGate[tid * 4 + 3] = make_float2( ca * ct,  sa * ct);
    }
    __syncthreads();

    // ---- stage 1: low-nibble product table (qubits 8..11 <-> bits 3..0) ----
    if (tid < 16) {
        float2 v = make_float2(1.0f, 0.0f);
        #pragma unroll
        for (int j = 0; j < 4; j++) {
            int q   = 8 + j;
            int bit = (tid >> (3 - j)) & 1;
            v = bit ? make_float2(v.y * ssn[q], -v.x * ssn[q])   // v * (-i sin)
                    : make_float2(v.x * sc[q],   v.y * sc[q]);   // v * cos
        }
        sL[tid] = v;
    }
    __syncthreads();

    // ---- stage 2: direct product-state init (RX embedding on |0..0>) ----
    {
        // thread t owns k = t*16 + lo; hi byte of k == t (qubits 0..7)
        float2 h = make_float2(1.0f, 0.0f);
        #pragma unroll
        for (int j = 0; j < 8; j++) {
            int bit = (tid >> (7 - j)) & 1;
            h = bit ? make_float2(h.y * ssn[j], -h.x * ssn[j])
                    : make_float2(h.x * sc[j],   h.y * sc[j]);
        }
        #pragma unroll
        for (int lo = 0; lo < 16; lo++) {
            sAmp[tid * APT + lo] = cmul(h, sL[lo]);
        }
    }
    __syncthreads();

    // ---- stage 3: variational layers ----
    for (int l = 0; l < NLAYERS; l++) {
        // Rot gates fused in pairs: qubits (qp, qp+1) act on ADJACENT bit
        // positions (pb+1, pb), pb = 10 - qp. One pass = 4-amp butterflies.
        for (int qp = 0; qp < NQ; qp += 2) {
            const int pb  = 10 - qp;
            const int gi  = (l * NQ + qp) * 4;
            const float2 A00 = sGate[gi + 0], A01 = sGate[gi + 1];
            const float2 A10 = sGate[gi + 2], A11 = sGate[gi + 3];
            const float2 B00 = sGate[gi + 4], B01 = sGate[gi + 5];
            const float2 B10 = sGate[gi + 6], B11 = sGate[gi + 7];
            const int lomask = (1 << pb) - 1;
            #pragma unroll
            for (int it = 0; it < DIM / 4 / THREADS; it++) {
                int g    = tid + it * THREADS;
                int base = ((g >> pb) << (pb + 2)) | (g & lomask);
                int i00 = base;
                int i01 = base | (1 << pb);
                int i10 = base | (2 << pb);
                int i11 = base | (3 << pb);
                float2 v00 = sAmp[i00], v01 = sAmp[i01];
                float2 v10 = sAmp[i10], v11 = sAmp[i11];
                // gate A on qubit qp (high bit of the pair)
                float2 t0 = cfma(A00, v00, cmul(A01, v10));
                float2 t2 = cfma(A10, v00, cmul(A11, v10));
                float2 t1 = cfma(A00, v01, cmul(A01, v11));
                float2 t3 = cfma(A10, v01, cmul(A11, v11));
                // gate B on qubit qp+1 (low bit of the pair)
                sAmp[i00] = cfma(B00, t0, cmul(B01, t1));
                sAmp[i01] = cfma(B10, t0, cmul(B11, t1));
                sAmp[i10] = cfma(B00, t2, cmul(B01, t3));
                sAmp[i11] = cfma(B10, t2, cmul(B11, t3));
            }
            __syncthreads();
        }
        // CNOT chain: control q (bit tpos+1), target q+1 (bit tpos).
        // Swap (control=1, target=0) <-> (control=1, target=1).
        for (int q = 0; q < NQ - 1; q++) {
            const int tpos = 10 - q;
            const int lomask = (1 << tpos) - 1;
            #pragma unroll
            for (int it = 0; it < DIM / 4 / THREADS; it++) {
                int p  = tid + it * THREADS;
                int i0 = ((p >> tpos) << (tpos + 2)) | (2 << tpos) | (p & lomask);
                int i1 = i0 | (1 << tpos);
                float2 a0 = sAmp[i0];
                float2 a1 = sAmp[i1];
                sAmp[i0] = a1;
                sAmp[i1] = a0;
            }
            __syncthreads();
        }
    }

    // ---- stage 4: probabilities -> <Z_q> ----
    // Thread t owns amps k = t*16+lo: qubits 0..7 signs fixed (bits of t),
    // qubits 8..11 vary with lo.
    float S = 0.0f, A8 = 0.0f, A9 = 0.0f, A10 = 0.0f, A11 = 0.0f;
    #pragma unroll
    for (int lo = 0; lo < 16; lo++) {
        float2 a = sAmp[tid * APT + lo];
        float p  = fmaf(a.x, a.x, a.y * a.y);
        S   += p;
        A8  += ((lo >> 3) & 1) ? -p : p;
        A9  += ((lo >> 2) & 1) ? -p : p;
        A10 += ((lo >> 1) & 1) ? -p : p;
        A11 += ( lo       & 1) ? -p : p;
    }
    float e[NQ];
    #pragma unroll
    for (int q = 0; q < 8; q++) e[q] = ((tid >> (7 - q)) & 1) ? -S : S;
    e[8] = A8; e[9] = A9; e[10] = A10; e[11] = A11;

    #pragma unroll
    for (int q = 0; q < NQ; q++) {
        float v = e[q];
        #pragma unroll
        for (int off = 16; off > 0; off >>= 1)
            v += __shfl_down_sync(0xffffffffu, v, off);
        if ((tid & 31) == 0) atomicAdd(&sExp[q], v);
    }
    __syncthreads();

    // ---- stage 5: readout mitigation, closed form ----
    // M = J - I  =>  M^{-1} = J/(n-1) - I  (symmetric)
    // p_q = (e_q+1)/2 ; out_q = 2*(S_p/(n-1) - p_q) - 1 = (E+12)/11 - e_q - 2
    if (tid < NQ) {
        float E = 0.0f;
        #pragma unroll
        for (int q = 0; q < NQ; q++) E += sExp[q];
        out[b * NQ + tid] = (E + 12.0f) * (1.0f / 11.0f) - sExp[tid] - 2.0f;
    }
}

extern "C" void kernel_launch(void* const* d_in, const int* in_sizes, int n_in,
                              void* d_out, int out_size) {
    const float* x      = (const float*)d_in[0];
    const float* params = (const float*)d_in[1];
    // defensive: identify params by its element count (6*12*3 = 216)
    if (n_in >= 2 && in_sizes[0] == NLAYERS * NQ * 3) {
        x      = (const float*)d_in[1];
        params = (const float*)d_in[0];
    }
    // allow full L1 carveout for shared so 6 CTAs/SM fit (single wave)
    cudaFuncSetAttribute(qsim_kernel,
                         cudaFuncAttributePreferredSharedMemoryCarveout, 100);
    int nblk = out_size / NQ;   // 768
    qsim_kernel<<<nblk, THREADS>>>(x, params, (float*)d_out);
}

// round 3
// speedup vs baseline: 1.6293x; 1.6293x over previous
#include <cuda_runtime.h>

#define NQ       12
#define DIM      4096            // 2^12
#define NLAYERS  6
#define NGATES   (NLAYERS * NQ)  // 72
#define THREADS  128
#define APT      (DIM / THREADS) // 32 amplitudes per thread

__device__ __forceinline__ float2 cmul(float2 a, float2 b) {
    return make_float2(fmaf(a.x, b.x, -a.y * b.y),
                       fmaf(a.x, b.y,  a.y * b.x));
}
__device__ __forceinline__ float2 cfma(float2 a, float2 b, float2 c) {
    // a*b + c
    return make_float2(fmaf(a.x, b.x, fmaf(-a.y, b.y, c.x)),
                       fmaf(a.x, b.y, fmaf( a.y, b.x, c.y)));
}

__global__ __launch_bounds__(THREADS)
void qsim_kernel(const float* __restrict__ x,
                 const float* __restrict__ params,
                 float* __restrict__ out) {
    __shared__ float2 sAmp[DIM];          // 32 KB statevector (physical layout)
    __shared__ float2 sGate[NGATES * 4];  // 72 Rot gates (2x2 complex)
    __shared__ float  sc[NQ], ssn[NQ];    // cos(x/2), sin(x/2)
    __shared__ float2 sL[32];             // product table, qubits 7..11
    __shared__ float  sExp[NQ];           // <Z_q> accumulators
    __shared__ unsigned sRowA[NQ];        // rows of A = T^l   (logical bit j of p)
    __shared__ unsigned sColB[NQ];        // cols of B = T^-l  (pair masks)

    const int tid = threadIdx.x;
    const int b   = blockIdx.x;

    // ---- stage 0: trig, gate matrices, GF(2) matrices, accumulators ----
    if (tid < NQ) {
        float xv = x[b * NQ + tid];
        sc[tid]   = cosf(0.5f * xv);
        ssn[tid]  = sinf(0.5f * xv);
        sExp[tid] = 0.0f;
        sRowA[tid] = 1u << tid;   // A = I
        sColB[tid] = 1u << tid;   // B = I
    }
    if (tid < NGATES) {
        float phi = params[tid * 3 + 0];
        float th  = params[tid * 3 + 1];
        float om  = params[tid * 3 + 2];
        float ct = cosf(0.5f * th), st = sinf(0.5f * th);
        float aa = 0.5f * (phi + om), bb = 0.5f * (phi - om);
        float ca = cosf(aa), sa = sinf(aa);
        float cb = cosf(bb), sb = sinf(bb);
        // Rot = [[ep*ct, -em*st], [conj(em)*st, conj(ep)*ct]]
        // ep = ca - i sa ; em = cb + i sb
        sGate[tid * 4 + 0] = make_float2( ca * ct, -sa * ct);
        sGate[tid * 4 + 1] = make_float2(-cb * st, -sb * st);
        sGate[tid * 4 + 2] = make_float2( cb * st, -sb * st);
        sGate[tid * 4 + 3] = make_float2( ca * ct,  sa * ct);
    }
    __syncthreads();

    // ---- stage 1: low-5-bit product table (qubits 7..11 <-> bits 4..0) ----
    if (tid < 32) {
        float2 v = make_float2(1.0f, 0.0f);
        #pragma unroll
        for (int j = 0; j < 5; j++) {
            int q   = 7 + j;
            int bit = (tid >> (4 - j)) & 1;
            v = bit ? make_float2(v.y * ssn[q], -v.x * ssn[q])  // v * (-i sin)
                    : make_float2(v.x * sc[q],   v.y * sc[q]);  // v * cos
        }
        sL[tid] = v;
    }
    __syncthreads();

    // ---- stage 2: direct product-state init (RX embedding on |0..0>) ----
    {
        // thread t owns p = t*32+lo; bits 11..5 of p == tid bits 6..0 (qubits 0..6)
        float2 h = make_float2(1.0f, 0.0f);
        #pragma unroll
        for (int j = 0; j < 7; j++) {
            int bit = (tid >> (6 - j)) & 1;
            h = bit ? make_float2(h.y * ssn[j], -h.x * ssn[j])
                    : make_float2(h.x * sc[j],   h.y * sc[j]);
        }
        #pragma unroll
        for (int lo = 0; lo < 32; lo++)
            sAmp[tid * APT + lo] = cmul(h, sL[lo]);
    }
    __syncthreads();

    // ---- stage 3: variational layers; CNOT chains folded into addressing ----
    // Invariant entering layer l: sPhys[p] = sLogical[A p], A = T^l, B = A^-1,
    // where T is the CNOT-chain bit map: (Ta)_j = XOR_{k>=j} a_k.
    for (int l = 0; l < NLAYERS; l++) {
        // Rot gates fused in pairs (qubits qp, qp+1) = logical bits (jA, jA-1).
        for (int qp = 0; qp < NQ; qp += 2) {
            const int jA = 11 - qp, jB = jA - 1;
            const unsigned mA = sColB[jA], mB = sColB[jB];  // physical pair masks
            const unsigned rA = sRowA[jA], rB = sRowA[jB];  // logical-bit selectors
            // Gaussian reduction -> two distinct pivot bits for coset reps
            unsigned m2 = mB;
            int p1 = 31 - __clz((int)mA);
            if ((m2 >> p1) & 1u) m2 ^= mA;
            int p2 = 31 - __clz((int)m2);
            const int pl = (p1 < p2) ? p1 : p2;
            const int ph = (p1 < p2) ? p2 : p1;
            const unsigned mlo = (1u << pl) - 1u;
            const unsigned mhi = (1u << ph) - 1u;

            const int gi = (l * NQ + qp) * 4;
            const float2 A00 = sGate[gi + 0], A01 = sGate[gi + 1];
            const float2 A10 = sGate[gi + 2], A11 = sGate[gi + 3];
            const float2 B00 = sGate[gi + 4], B01 = sGate[gi + 5];
            const float2 B10 = sGate[gi + 6], B11 = sGate[gi + 7];

            #pragma unroll
            for (int it = 0; it < DIM / 4 / THREADS; it++) {  // 8 groups/thread
                unsigned g   = tid + it * THREADS;            // 10-bit coset id
                unsigned t1  = ((g >> pl) << (pl + 1)) | (g & mlo);
                unsigned rep = ((t1 >> ph) << (ph + 1)) | (t1 & mhi);
                // canonicalize: force logical bits (jA, jB) of r0 to (0,0)
                unsigned r0 = rep;
                if (__popc(rA & rep) & 1) r0 ^= mA;
                if (__popc(rB & rep) & 1) r0 ^= mB;
                const unsigned i00 = r0;
                const unsigned i10 = r0 ^ mA;
                const unsigned i01 = r0 ^ mB;
                const unsigned i11 = i10 ^ mB;
                float2 v00 = sAmp[i00], v10 = sAmp[i10];
                float2 v01 = sAmp[i01], v11 = sAmp[i11];
                // gate A on logical bit jA (qubit qp)
                float2 u0 = cfma(A00, v00, cmul(A01, v10));
                float2 u2 = cfma(A10, v00, cmul(A11, v10));
                float2 u1 = cfma(A00, v01, cmul(A01, v11));
                float2 u3 = cfma(A10, v01, cmul(A11, v11));
                // gate B on logical bit jB (qubit qp+1)
                sAmp[i00] = cfma(B00, u0, cmul(B01, u1));
                sAmp[i01] = cfma(B10, u0, cmul(B11, u1));
                sAmp[i10] = cfma(B00, u2, cmul(B01, u3));
                sAmp[i11] = cfma(B10, u2, cmul(B11, u3));
            }
            __syncthreads();
        }
        // CNOT chain as matrix update:  A <- T*A ;  B <- B*T^-1
        // row_j(T*A) = XOR_{k>=j} row_k(A)      (suffix XOR)
        // col_q(B*T^-1) = col_q(B) ^ col_{q-1}(B)  (q>=1)
        if (tid == 0) {
            unsigned acc = 0;
            #pragma unroll
            for (int j = NQ - 1; j >= 0; j--) { acc ^= sRowA[j]; sRowA[j] = acc; }
            #pragma unroll
            for (int q = NQ - 1; q >= 1; q--) sColB[q] ^= sColB[q - 1];
        }
        __syncthreads();
    }

    // ---- stage 4: probabilities -> <Z_q> with permuted sign masks ----
    // <Z_q> sign at physical p = (-1)^parity(rowA_final[11-q] & p)
    unsigned rq[NQ];
    #pragma unroll
    for (int q = 0; q < NQ; q++) rq[q] = sRowA[11 - q];

    float e[NQ];
    #pragma unroll
    for (int q = 0; q < NQ; q++) e[q] = 0.0f;

    #pragma unroll
    for (int lo = 0; lo < APT; lo++) {
        unsigned p = tid * APT + lo;
        float2 a = sAmp[p];
        float pr = fmaf(a.x, a.x, a.y * a.y);
        #pragma unroll
        for (int q = 0; q < NQ; q++)
            e[q] += (__popc(rq[q] & p) & 1) ? -pr : pr;
    }

    #pragma unroll
    for (int q = 0; q < NQ; q++) {
        float v = e[q];
        #pragma unroll
        for (int off = 16; off > 0; off >>= 1)
            v += __shfl_down_sync(0xffffffffu, v, off);
        if ((tid & 31) == 0) atomicAdd(&sExp[q], v);
    }
    __syncthreads();

    // ---- stage 5: readout mitigation, closed form ----
    // M = J - I => M^-1 = J/(n-1) - I ; out_q = (E+12)/11 - e_q - 2
    if (tid < NQ) {
        float E = 0.0f;
        #pragma unroll
        for (int q = 0; q < NQ; q++) E += sExp[q];
        out[b * NQ + tid] = (E + 12.0f) * (1.0f / 11.0f) - sExp[tid] - 2.0f;
    }
}

extern "C" void kernel_launch(void* const* d_in, const int* in_sizes, int n_in,
                              void* d_out, int out_size) {
    const float* x      = (const float*)d_in[0];
    const float* params = (const float*)d_in[1];
    if (n_in >= 2 && in_sizes[0] == NLAYERS * NQ * 3) {
        x      = (const float*)d_in[1];
        params = (const float*)d_in[0];
    }
    cudaFuncSetAttribute(qsim_kernel,
                         cudaFuncAttributePreferredSharedMemoryCarveout, 100);
    int nblk = out_size / NQ;   // 768
    qsim_kernel<<<nblk, THREADS>>>(x, params, (float*)d_out);
}

// round 4
// speedup vs baseline: 1.7137x; 1.0518x over previous
#include <cuda_runtime.h>

#define NQ       12
#define DIM      4096            // 2^12
#define NLAYERS  6
#define NGATES   (NLAYERS * NQ)  // 72
#define THREADS  128
#define APT      (DIM / THREADS) // 32 amplitudes per thread

__device__ __forceinline__ float2 cmul(float2 a, float2 b) {
    return make_float2(fmaf(a.x, b.x, -a.y * b.y),
                       fmaf(a.x, b.y,  a.y * b.x));
}
__device__ __forceinline__ float2 cfma(float2 a, float2 b, float2 c) {
    // a*b + c
    return make_float2(fmaf(a.x, b.x, fmaf(-a.y, b.y, c.x)),
                       fmaf(a.x, b.y, fmaf( a.y, b.x, c.y)));
}

__global__ __launch_bounds__(THREADS, 5)
void qsim_kernel(const float* __restrict__ x,
                 const float* __restrict__ params,
                 float* __restrict__ out) {
    __shared__ float2 sAmp[DIM];          // 32 KB statevector (physical layout)
    __shared__ float2 sGate[NGATES * 4];  // 72 Rot gates (2x2 complex)
    __shared__ float  sc[NQ], ssn[NQ];    // cos(x/2), sin(x/2)
    __shared__ float2 sL[32];             // product table, qubits 7..11
    __shared__ float  sExp[NQ];           // <Z_q> accumulators
    __shared__ unsigned sRowA[NQ];        // rows of A = T^l   (logical bit j at phys p)
    __shared__ unsigned sColB[NQ];        // cols of B = T^-l  (pair masks)

    const int tid = threadIdx.x;
    const int b   = blockIdx.x;

    // ---- stage 0: trig, gate matrices, GF(2) matrices, accumulators ----
    if (tid < NQ) {
        float xv = x[b * NQ + tid];
        sc[tid]    = cosf(0.5f * xv);
        ssn[tid]   = sinf(0.5f * xv);
        sExp[tid]  = 0.0f;
        sRowA[tid] = 1u << tid;   // A = I
        sColB[tid] = 1u << tid;   // B = I
    }
    if (tid < NGATES) {
        float phi = params[tid * 3 + 0];
        float th  = params[tid * 3 + 1];
        float om  = params[tid * 3 + 2];
        float ct = cosf(0.5f * th), st = sinf(0.5f * th);
        float aa = 0.5f * (phi + om), bb = 0.5f * (phi - om);
        float ca = cosf(aa), sa = sinf(aa);
        float cb = cosf(bb), sb = sinf(bb);
        // Rot = [[ep*ct, -em*st], [conj(em)*st, conj(ep)*ct]]
        sGate[tid * 4 + 0] = make_float2( ca * ct, -sa * ct);
        sGate[tid * 4 + 1] = make_float2(-cb * st, -sb * st);
        sGate[tid * 4 + 2] = make_float2( cb * st, -sb * st);
        sGate[tid * 4 + 3] = make_float2( ca * ct,  sa * ct);
    }
    __syncthreads();

    // ---- stage 1: low-5-bit product table (qubits 7..11 <-> bits 4..0) ----
    if (tid < 32) {
        float2 v = make_float2(1.0f, 0.0f);
        #pragma unroll
        for (int j = 0; j < 5; j++) {
            int q   = 7 + j;
            int bit = (tid >> (4 - j)) & 1;
            v = bit ? make_float2(v.y * ssn[q], -v.x * ssn[q])  // v * (-i sin)
                    : make_float2(v.x * sc[q],   v.y * sc[q]);  // v * cos
        }
        sL[tid] = v;
    }
    __syncthreads();

    // ---- stage 2: direct product-state init (RX embedding on |0..0>) ----
    {
        float2 h = make_float2(1.0f, 0.0f);
        #pragma unroll
        for (int j = 0; j < 7; j++) {
            int bit = (tid >> (6 - j)) & 1;
            h = bit ? make_float2(h.y * ssn[j], -h.x * ssn[j])
                    : make_float2(h.x * sc[j],   h.y * sc[j]);
        }
        #pragma unroll
        for (int lo = 0; lo < 32; lo++)
            sAmp[tid * APT + lo] = cmul(h, sL[lo]);
    }
    __syncthreads();

    // ---- stage 3: variational layers; 4 gates fused per pass ----
    // Invariant entering layer l: sPhys[p] = sLogical[A p], A = T^l, B = A^-1.
    for (int l = 0; l < NLAYERS; l++) {
        for (int qp = 0; qp < NQ; qp += 4) {
            const int jA = 11 - qp;
            const unsigned mA = sColB[jA],     mB = sColB[jA - 1];
            const unsigned mC = sColB[jA - 2], mD = sColB[jA - 3];
            const unsigned rA = sRowA[jA],     rB = sRowA[jA - 1];
            const unsigned rC = sRowA[jA - 2], rD = sRowA[jA - 3];

            // Gaussian reduction -> 4 distinct pivot bits
            unsigned w0 = mA;
            int q0 = 31 - __clz((int)w0);
            unsigned w1 = mB;
            if ((w1 >> q0) & 1u) w1 ^= w0;
            int q1 = 31 - __clz((int)w1);
            unsigned w2 = mC;
            if ((w2 >> q0) & 1u) w2 ^= w0;
            if ((w2 >> q1) & 1u) w2 ^= w1;
            int q2 = 31 - __clz((int)w2);
            unsigned w3 = mD;
            if ((w3 >> q0) & 1u) w3 ^= w0;
            if ((w3 >> q1) & 1u) w3 ^= w1;
            if ((w3 >> q2) & 1u) w3 ^= w2;
            int q3 = 31 - __clz((int)w3);
            // sort pivots ascending (5-comparator network)
            int t;
            if (q0 > q1) { t = q0; q0 = q1; q1 = t; }
            if (q2 > q3) { t = q2; q2 = q3; q3 = t; }
            if (q0 > q2) { t = q0; q0 = q2; q2 = t; }
            if (q1 > q3) { t = q1; q1 = q3; q3 = t; }
            if (q1 > q2) { t = q1; q1 = q2; q2 = t; }
            const unsigned m0 = (1u << q0) - 1u, m1 = (1u << q1) - 1u;
            const unsigned m2 = (1u << q2) - 1u, m3 = (1u << q3) - 1u;

            const int gi = (l * NQ + qp) * 4;

            #pragma unroll
            for (int it = 0; it < DIM / 16 / THREADS; it++) {  // 2 groups/thread
                unsigned g = tid + it * THREADS;               // 8-bit coset id
                // insert zero bits at sorted pivot positions
                unsigned rep = ((g   >> q0) << (q0 + 1)) | (g   & m0);
                rep = ((rep >> q1) << (q1 + 1)) | (rep & m1);
                rep = ((rep >> q2) << (q2 + 1)) | (rep & m2);
                rep = ((rep >> q3) << (q3 + 1)) | (rep & m3);
                // canonicalize: logical bits jA..jD of r0 -> 0 (independent: r_j.m_k = delta)
                unsigned r0 = rep;
                if (__popc(rA & rep) & 1) r0 ^= mA;
                if (__popc(rB & rep) & 1) r0 ^= mB;
                if (__popc(rC & rep) & 1) r0 ^= mC;
                if (__popc(rD & rep) & 1) r0 ^= mD;

                float2 v[16];
                #pragma unroll
                for (int k = 0; k < 16; k++) {
                    unsigned off = ((k & 8) ? mA : 0u) ^ ((k & 4) ? mB : 0u)
                                 ^ ((k & 2) ? mC : 0u) ^ ((k & 1) ? mD : 0u);
                    v[k] = sAmp[r0 ^ off];
                }
                {   // gate A (logical bit jA = group bit 3)
                    const float2 G00 = sGate[gi + 0], G01 = sGate[gi + 1];
                    const float2 G10 = sGate[gi + 2], G11 = sGate[gi + 3];
                    #pragma unroll
                    for (int k = 0; k < 8; k++) {
                        float2 v0 = v[k], v1 = v[k + 8];
                        v[k]     = cfma(G00, v0, cmul(G01, v1));
                        v[k + 8] = cfma(G10, v0, cmul(G11, v1));
                    }
                }
                {   // gate B (group bit 2)
                    const float2 G00 = sGate[gi + 4], G01 = sGate[gi + 5];
                    const float2 G10 = sGate[gi + 6], G11 = sGate[gi + 7];
                    #pragma unroll
                    for (int h = 0; h < 16; h += 8)
                        #pragma unroll
                        for (int k = 0; k < 4; k++) {
                            float2 v0 = v[h + k], v1 = v[h + k + 4];
                            v[h + k]     = cfma(G00, v0, cmul(G01, v1));
                            v[h + k + 4] = cfma(G10, v0, cmul(G11, v1));
                        }
                }
                {   // gate C (group bit 1)
                    const float2 G00 = sGate[gi + 8],  G01 = sGate[gi + 9];
                    const float2 G10 = sGate[gi + 10], G11 = sGate[gi + 11];
                    #pragma unroll
                    for (int h = 0; h < 16; h += 4)
                        #pragma unroll
                        for (int k = 0; k < 2; k++) {
                            float2 v0 = v[h + k], v1 = v[h + k + 2];
                            v[h + k]     = cfma(G00, v0, cmul(G01, v1));
                            v[h + k + 2] = cfma(G10, v0, cmul(G11, v1));
                        }
                }
                {   // gate D (group bit 0)
                    const float2 G00 = sGate[gi + 12], G01 = sGate[gi + 13];
                    const float2 G10 = sGate[gi + 14], G11 = sGate[gi + 15];
                    #pragma unroll
                    for (int k = 0; k < 16; k += 2) {
                        float2 v0 = v[k], v1 = v[k + 1];
                        v[k]     = cfma(G00, v0, cmul(G01, v1));
                        v[k + 1] = cfma(G10, v0, cmul(G11, v1));
                    }
                }
                #pragma unroll
                for (int k = 0; k < 16; k++) {
                    unsigned off = ((k & 8) ? mA : 0u) ^ ((k & 4) ? mB : 0u)
                                 ^ ((k & 2) ? mC : 0u) ^ ((k & 1) ? mD : 0u);
                    sAmp[r0 ^ off] = v[k];
                }
            }
            __syncthreads();
        }
        // CNOT chain as matrix update:  A <- T*A ;  B <- B*T^-1
        if (tid == 0) {
            unsigned acc = 0;
            #pragma unroll
            for (int j = NQ - 1; j >= 0; j--) { acc ^= sRowA[j]; sRowA[j] = acc; }
            #pragma unroll
            for (int q = NQ - 1; q >= 1; q--) sColB[q] ^= sColB[q - 1];
        }
        __syncthreads();
    }

    // ---- stage 4: probabilities -> <Z_q> with permuted sign masks ----
    unsigned rq[NQ];
    #pragma unroll
    for (int q = 0; q < NQ; q++) rq[q] = sRowA[11 - q];

    float e[NQ];
    #pragma unroll
    for (int q = 0; q < NQ; q++) e[q] = 0.0f;

    #pragma unroll
    for (int lo = 0; lo < APT; lo++) {
        unsigned p = tid * APT + lo;
        float2 a = sAmp[p];
        float pr = fmaf(a.x, a.x, a.y * a.y);
        #pragma unroll
        for (int q = 0; q < NQ; q++)
            e[q] += (__popc(rq[q] & p) & 1) ? -pr : pr;
    }

    #pragma unroll
    for (int q = 0; q < NQ; q++) {
        float v = e[q];
        #pragma unroll
        for (int off = 16; off > 0; off >>= 1)
            v += __shfl_down_sync(0xffffffffu, v, off);
        if ((tid & 31) == 0) atomicAdd(&sExp[q], v);
    }
    __syncthreads();

    // ---- stage 5: readout mitigation, closed form ----
    // M = J - I => M^-1 = J/(n-1) - I ; out_q = (E+12)/11 - e_q - 2
    if (tid < NQ) {
        float E = 0.0f;
        #pragma unroll
        for (int q = 0; q < NQ; q++) E += sExp[q];
        out[b * NQ + tid] = (E + 12.0f) * (1.0f / 11.0f) - sExp[tid] - 2.0f;
    }
}

extern "C" void kernel_launch(void* const* d_in, const int* in_sizes, int n_in,
                              void* d_out, int out_size) {
    const float* x      = (const float*)d_in[0];
    const float* params = (const float*)d_in[1];
    if (n_in >= 2 && in_sizes[0] == NLAYERS * NQ * 3) {
        x      = (const float*)d_in[1];
        params = (const float*)d_in[0];
    }
    cudaFuncSetAttribute(qsim_kernel,
                         cudaFuncAttributePreferredSharedMemoryCarveout, 100);
    int nblk = out_size / NQ;   // 768
    qsim_kernel<<<nblk, THREADS>>>(x, params, (float*)d_out);
}